// round 1
// baseline (speedup 1.0000x reference)
#include <cuda_runtime.h>

// Bilinear grid-sample (align_corners=True semantics matching the reference):
// img  [B=8, H=512, W=512, C=32] f32
// grid [B, H, W, 2] f32 in [-1,1], grid[...,0]=x, grid[...,1]=y
// out  [B, H, W, C] f32
//
// Layout: 8 threads per output pixel; each thread covers 4 channels (float4).
// Each of the 4 corner gathers is one fully-coalesced 128B line per pixel-warp-slice.

#define B_ 8
#define H_ 512
#define W_ 512
#define C_ 32
#define NPIX (B_ * H_ * W_)            // 2,097,152
#define THREADS_PER_PIX 8              // C/4
#define NTHREADS (NPIX * THREADS_PER_PIX)

__global__ __launch_bounds__(256, 8)
void grid_sample_kernel(const float4* __restrict__ img4,
                        const float2* __restrict__ grid2,
                        float4* __restrict__ out4)
{
    int gtid = blockIdx.x * blockDim.x + threadIdx.x;
    if (gtid >= NTHREADS) return;

    int pix = gtid >> 3;        // pixel index in [0, NPIX)
    int cb  = gtid & 7;         // channel block (float4 index within pixel)

    // batch index: H*W = 262144 = 2^18
    int b = pix >> 18;

    float2 g = grid2[pix];      // g.x = x-coord, g.y = y-coord (broadcast across 8 lanes)

    const float max_x = (float)(W_ - 1);
    const float max_y = (float)(H_ - 1);

    float x = 0.5f * ((g.x + 1.0f) * max_x);
    float y = 0.5f * ((g.y + 1.0f) * max_y);

    float x0f_ = floorf(x);
    float y0f_ = floorf(y);
    int x0 = (int)x0f_;
    int y0 = (int)y0f_;
    int x1 = x0 + 1;
    int y1 = y0 + 1;

    int x0c = min(max(x0, 0), W_ - 1);
    int x1c = min(max(x1, 0), W_ - 1);
    int y0c = min(max(y0, 0), H_ - 1);
    int y1c = min(max(y1, 0), H_ - 1);

    float x0f = (float)x0c;
    float x1f = (float)x1c;
    float y0f = (float)y0c;
    float y1f = (float)y1c;

    float wa = (x1f - x) * (y1f - y);
    float wb = (x1f - x) * (y - y0f);
    float wc = (x - x0f) * (y1f - y);
    float wd = (x - x0f) * (y - y0f);

    // float4-granular addressing: pixel (b, yy, xx) starts at
    // ((b*H + yy)*W + xx) * (C/4) float4's.
    long bbase = (long)b << 18;  // b * H * W
    const float4* pa = img4 + (((bbase + (long)y0c * W_ + x0c) << 3) + cb);
    const float4* pb = img4 + (((bbase + (long)y1c * W_ + x0c) << 3) + cb);
    const float4* pc = img4 + (((bbase + (long)y0c * W_ + x1c) << 3) + cb);
    const float4* pd = img4 + (((bbase + (long)y1c * W_ + x1c) << 3) + cb);

    // Issue all 4 gathers before consuming any (MLP=4 per thread).
    float4 Ia = *pa;
    float4 Ib = *pb;
    float4 Ic = *pc;
    float4 Id = *pd;

    float4 o;
    o.x = wa * Ia.x + wb * Ib.x + wc * Ic.x + wd * Id.x;
    o.y = wa * Ia.y + wb * Ib.y + wc * Ic.y + wd * Id.y;
    o.z = wa * Ia.z + wb * Ib.z + wc * Ic.z + wd * Id.z;
    o.w = wa * Ia.w + wb * Ib.w + wc * Ic.w + wd * Id.w;

    out4[((long)pix << 3) + cb] = o;
}

extern "C" void kernel_launch(void* const* d_in, const int* in_sizes, int n_in,
                              void* d_out, int out_size)
{
    const float4* img4  = (const float4*)d_in[0];
    const float2* grid2 = (const float2*)d_in[1];
    float4* out4 = (float4*)d_out;

    const int threads = 256;
    const int blocks = (NTHREADS + threads - 1) / threads;  // 65536
    grid_sample_kernel<<<blocks, threads>>>(img4, grid2, out4);
}

// round 2
// speedup vs baseline: 1.2791x; 1.2791x over previous
#include <cuda_runtime.h>

// Bilinear grid-sample, 2 pixels per thread for doubled memory-level parallelism.
// img  [B=8, H=512, W=512, C=32] f32   (pixel row = 128B, exactly one L2 line)
// grid [B, H, W, 2] f32 in [-1,1]
// out  [B, H, W, C] f32
//
// Layout: 8 threads per pixel (float4 channels), each thread handles 2 ADJACENT
// pixels -> one float4 grid load serves both, 8 independent 128B corner gathers
// in flight per thread. Streaming stores keep output from thrashing L2 (image
// working set of the active batch stays resident).

#define B_ 8
#define H_ 512
#define W_ 512
#define C_ 32
#define NPIX (B_ * H_ * W_)          // 2,097,152
#define NPAIR (NPIX / 2)             // 1,048,576
#define NTHREADS (NPAIR * 8)         // 8,388,608

__device__ __forceinline__ void pixel_setup(
    float gx, float gy, int bbase, int cb,
    unsigned& oa, unsigned& ob, unsigned& oc, unsigned& od,
    float& wa, float& wb, float& wc, float& wd)
{
    // unnormalize: 0.5*((g+1)*511) = g*255.5 + 255.5
    float x = fmaf(gx, 255.5f, 255.5f);
    float y = fmaf(gy, 255.5f, 255.5f);

    float xf = floorf(x);
    float yf = floorf(y);
    int x0 = (int)xf;
    int y0 = (int)yf;

    int x0c = min(max(x0, 0), W_ - 1);
    int x1c = min(max(x0 + 1, 0), W_ - 1);
    int y0c = min(max(y0, 0), H_ - 1);
    int y1c = min(max(y0 + 1, 0), H_ - 1);

    float dx0 = (float)x0c, dx1 = (float)x1c;
    float dy0 = (float)y0c, dy1 = (float)y1c;

    wa = (dx1 - x) * (dy1 - y);
    wb = (dx1 - x) * (y - dy0);
    wc = (x - dx0) * (dy1 - y);
    wd = (x - dx0) * (y - dy0);

    // byte offsets into img (max 2^28-1, fits unsigned)
    unsigned r0 = (unsigned)(bbase + (y0c << 9));   // row base in pixels
    unsigned r1 = (unsigned)(bbase + (y1c << 9));
    oa = ((((r0 + x0c) << 3) + cb) << 4);
    ob = ((((r1 + x0c) << 3) + cb) << 4);
    oc = ((((r0 + x1c) << 3) + cb) << 4);
    od = ((((r1 + x1c) << 3) + cb) << 4);
}

__global__ __launch_bounds__(128, 9)
void grid_sample_kernel(const char* __restrict__ img_bytes,
                        const float4* __restrict__ grid4,
                        float4* __restrict__ out4)
{
    int gtid = blockIdx.x * 128 + threadIdx.x;
    int pair = gtid >> 3;
    int cb   = gtid & 7;
    int pix0 = pair << 1;              // even pixel; pairs never straddle a batch
    int bbase = (pix0 >> 18) << 18;    // b * H * W

    float4 g = __ldg(&grid4[pair]);    // (x0, y0, x1, y1) for pixels pix0, pix0+1

    unsigned oa0, ob0, oc0, od0, oa1, ob1, oc1, od1;
    float wa0, wb0, wc0, wd0, wa1, wb1, wc1, wd1;
    pixel_setup(g.x, g.y, bbase, cb, oa0, ob0, oc0, od0, wa0, wb0, wc0, wd0);
    pixel_setup(g.z, g.w, bbase, cb, oa1, ob1, oc1, od1, wa1, wb1, wc1, wd1);

    // Issue all 8 gathers before consuming any (MLP = 8 per thread).
    float4 Ia0 = __ldg((const float4*)(img_bytes + oa0));
    float4 Ib0 = __ldg((const float4*)(img_bytes + ob0));
    float4 Ic0 = __ldg((const float4*)(img_bytes + oc0));
    float4 Id0 = __ldg((const float4*)(img_bytes + od0));
    float4 Ia1 = __ldg((const float4*)(img_bytes + oa1));
    float4 Ib1 = __ldg((const float4*)(img_bytes + ob1));
    float4 Ic1 = __ldg((const float4*)(img_bytes + oc1));
    float4 Id1 = __ldg((const float4*)(img_bytes + od1));

    float4 o0;
    o0.x = fmaf(wa0, Ia0.x, fmaf(wb0, Ib0.x, fmaf(wc0, Ic0.x, wd0 * Id0.x)));
    o0.y = fmaf(wa0, Ia0.y, fmaf(wb0, Ib0.y, fmaf(wc0, Ic0.y, wd0 * Id0.y)));
    o0.z = fmaf(wa0, Ia0.z, fmaf(wb0, Ib0.z, fmaf(wc0, Ic0.z, wd0 * Id0.z)));
    o0.w = fmaf(wa0, Ia0.w, fmaf(wb0, Ib0.w, fmaf(wc0, Ic0.w, wd0 * Id0.w)));
    __stcs(&out4[((long)pix0 << 3) + cb], o0);

    float4 o1;
    o1.x = fmaf(wa1, Ia1.x, fmaf(wb1, Ib1.x, fmaf(wc1, Ic1.x, wd1 * Id1.x)));
    o1.y = fmaf(wa1, Ia1.y, fmaf(wb1, Ib1.y, fmaf(wc1, Ic1.y, wd1 * Id1.y)));
    o1.z = fmaf(wa1, Ia1.z, fmaf(wb1, Ib1.z, fmaf(wc1, Ic1.z, wd1 * Id1.z)));
    o1.w = fmaf(wa1, Ia1.w, fmaf(wb1, Ib1.w, fmaf(wc1, Ic1.w, wd1 * Id1.w)));
    __stcs(&out4[(((long)pix0 + 1) << 3) + cb], o1);
}

extern "C" void kernel_launch(void* const* d_in, const int* in_sizes, int n_in,
                              void* d_out, int out_size)
{
    const char*   img_bytes = (const char*)d_in[0];
    const float4* grid4     = (const float4*)d_in[1];
    float4* out4 = (float4*)d_out;

    const int threads = 128;
    const int blocks = NTHREADS / threads;  // 65536, exact
    grid_sample_kernel<<<blocks, threads>>>(img_bytes, grid4, out4);
}